// round 13
// baseline (speedup 1.0000x reference)
#include <cuda_runtime.h>
#include <cuda_bf16.h>

// Problem constants (fixed by the dataset): B=256, T=512, K=128
#define Bn 256
#define Tn 512
#define Kn 128

// Device scratch (no allocs allowed).
__device__ float g_partial[Bn];
__device__ int   g_perm[Bn];   // g_perm[rank] = batch index, by seq_len
__device__ int   g_done;       // zero-init; last CTA resets to 0 each run

// ---- scheduler: grid=32 x 256 threads; warp w ranks batch 8*bx+w ----------
__global__ void crf_sched_kernel(const int* __restrict__ seq_lens)
{
    const int lane = threadIdx.x & 31;
    const int i    = blockIdx.x * 8 + (threadIdx.x >> 5);
    const int Li   = seq_lens[i];
    int r = 0;
    #pragma unroll
    for (int kk = 0; kk < 8; kk++) {
        int k  = lane + 32 * kk;
        int Lk = seq_lens[k];
        r += (Lk < Li) || (Lk == Li && k < i);   // unique ranks
    }
    #pragma unroll
    for (int o = 16; o; o >>= 1) r += __shfl_xor_sync(0xffffffffu, r, o);
    if (lane == 0) g_perm[r] = i;
}

__device__ __forceinline__ float frcp(float x) {
    float q; asm("rcp.approx.f32 %0, %1;" : "=f"(q) : "f"(x));
    return q;
}

// One scan step (phase s). Matvec warps (0-3): thread j = tau owns the FULL
// column: 16 LDS.128 broadcast + 64 HFMA2 into 8 accumulators (8-deep) +
// pure-bf16 tail with NO shuffle. cj comes from sh_ce (written by helpers one
// phase earlier; parity-separated buffers -> race-free). Renorm (1-in-4)
// scales cj by rcp(beta[0]) -- read at phase start, hidden under FMA issue;
// S += logf(r) keeps the LSE shift identity exact. Helper warps (4-7):
// thread j publishes cj for step s+1 = bf16x2(exp(logits[s+1, j])) and
// refills its raw prefetch register (4 steps ahead).
#define CRF_STEP(RDBUF_, WRBUF_, REN_, HREG_, NROW_) do {                    \
    if (isMat) {                                                             \
        unsigned ceu_ = sh_ce[RDBUF_][j];                                    \
        __nv_bfloat162 cj2_ = *(__nv_bfloat162*)&ceu_;                       \
        if (REN_) {                                                          \
            float rr_ = __bfloat162float(sh_beta[cur][0]);                   \
            S += __logf(rr_);                                                \
            cj2_ = __hmul2(cj2_, __float2bfloat162_rn(frcp(rr_)));           \
        }                                                                    \
        const uint4* ap_ = (const uint4*)sh_beta[cur];                       \
        __nv_bfloat162 z_; z_.x = __float2bfloat16(0.f); z_.y = z_.x;        \
        __nv_bfloat162 a0_=z_,a1_=z_,a2_=z_,a3_=z_,a4_=z_,a5_=z_,a6_=z_,a7_=z_; \
        _Pragma("unroll")                                                    \
        for (int L_ = 0; L_ < 16; L_ += 2) {                                 \
            uint4 v_ = ap_[L_];          /* LDS.128 pure broadcast */        \
            uint4 w_ = ap_[L_ + 1];                                          \
            a0_ = __hfma2(*(__nv_bfloat162*)&v_.x, eT2[4*L_+0], a0_);        \
            a1_ = __hfma2(*(__nv_bfloat162*)&v_.y, eT2[4*L_+1], a1_);        \
            a2_ = __hfma2(*(__nv_bfloat162*)&v_.z, eT2[4*L_+2], a2_);        \
            a3_ = __hfma2(*(__nv_bfloat162*)&v_.w, eT2[4*L_+3], a3_);        \
            a4_ = __hfma2(*(__nv_bfloat162*)&w_.x, eT2[4*L_+4], a4_);        \
            a5_ = __hfma2(*(__nv_bfloat162*)&w_.y, eT2[4*L_+5], a5_);        \
            a6_ = __hfma2(*(__nv_bfloat162*)&w_.z, eT2[4*L_+6], a6_);        \
            a7_ = __hfma2(*(__nv_bfloat162*)&w_.w, eT2[4*L_+7], a7_);        \
        }                                                                    \
        __nv_bfloat162 s_ =                                                  \
            __hadd2(__hadd2(__hadd2(a0_, a1_), __hadd2(a2_, a3_)),           \
                    __hadd2(__hadd2(a4_, a5_), __hadd2(a6_, a7_)));          \
        s_ = __hmul2(s_, cj2_);               /* mul before horizontal */    \
        __nv_bfloat162 sw_ = __lowhigh2highlow(s_);                          \
        __nv_bfloat162 tot_ = __hadd2(s_, sw_);                              \
        sh_beta[cur ^ 1][j] = tot_.x;                                        \
    } else {                                                                 \
        __nv_bfloat162 ce_ = __float2bfloat162_rn(__expf(HREG_));            \
        sh_ce[WRBUF_][j] = *(unsigned*)&ce_;                                 \
        HREG_ = NROW_;                        /* refill raw prefetch */      \
    }                                                                        \
    __syncthreads();                          /* the ONLY barrier/step */    \
    cur ^= 1;                                                                \
} while (0)

// grid=128 CTAs, 256 threads, one CTA/SM. CTA c runs batches perm[c] then
// perm[255-c] sequentially (balanced pairs: step sums ~ T+1). Warps 0-3 =
// matvec (full column per thread), warps 4-7 = helpers (logit exp pipeline).
__global__ __launch_bounds__(256, 1) void crf_forward_kernel(
    const float* __restrict__ logits,   // [B, T, K]
    const int*   __restrict__ labels,   // [B, T]
    const int*   __restrict__ seq_lens, // [B]
    const float* __restrict__ trans,    // [K, K] trans[i*K + j]
    float* __restrict__ out)
{
    __shared__ __align__(16) __nv_bfloat16 sh_beta[2][Kn];
    __shared__ unsigned sh_ce[2][Kn];    // packed bf16x2 cj, double-buffered
    __shared__ float sh_wred[8];
    __shared__ int   sh_last;

    const int c     = blockIdx.x;         // 0..127
    const int tau   = threadIdx.x;        // 0..255
    const bool isMat = (tau < Kn);        // warps 0-3
    const int j     = isMat ? tau : (tau - Kn);   // column 0..127
    const int lane  = tau & 31;
    const int warp  = tau >> 5;

    const int bA = g_perm[c];
    const int bB = g_perm[Bn - 1 - c];

    // expT[:, j] as 64 bf16x2 over row-pairs (matvec threads only)
    __nv_bfloat162 eT2[64];
    if (isMat) {
        #pragma unroll
        for (int k = 0; k < 64; k++) {
            float e0 = __expf(trans[(2 * k)     * Kn + j]);   // coalesced
            float e1 = __expf(trans[(2 * k + 1) * Kn + j]);
            eT2[k] = __floats2bfloat162_rn(e0, e1);
        }
    }

    for (int p = 0; p < 2; p++) {
        const int b = p ? bB : bA;
        const int    Tlen = seq_lens[b];                  // 1..512
        const float* lg   = logits + (size_t)b * Tn * Kn;
        const int*   lb   = labels + b * Tn;

        // ---------- gold-path score: unary + pairwise (fp32 exact) --------
        float sc = 0.f;
        for (int t = tau; t < Tlen; t += 256) {
            int y = lb[t];
            sc += lg[t * Kn + y];
            if (t >= 1) sc += trans[lb[t - 1] * Kn + y];
        }
        #pragma unroll
        for (int o = 16; o; o >>= 1) sc += __shfl_xor_sync(0xffffffffu, sc, o);
        if (lane == 0) sh_wred[warp] = sc;

        #define ROW(tt) lg[(((tt) < Tn) ? (tt) : (Tn - 1)) * Kn + j]
        // Prologue: matvec writes beta_0; helpers write cj for step 1 into
        // buf 1 and load raw rows 2..5 (cj for steps 2..5 made in phases 1..4).
        float h0 = 0.f, h1 = 0.f, h2 = 0.f, h3 = 0.f;
        if (isMat) {
            sh_beta[0][j] = __float2bfloat16(__expf(lg[j]));
        } else {
            __nv_bfloat162 ce0 = __float2bfloat162_rn(__expf(ROW(1)));
            sh_ce[1][j] = *(unsigned*)&ce0;
            h0 = ROW(2); h1 = ROW(3); h2 = ROW(4); h3 = ROW(5);
        }
        __syncthreads();
        float score = 0.f;
        #pragma unroll
        for (int w = 0; w < 8; w++) score += sh_wred[w];

        // ---------- forward recursion, 4x unrolled, renorm 1-in-4 ---------
        // t stays ≡ 1 (mod 4): slots read ce buf 1,0,1,0 / write 0,1,0,1.
        float S   = 0.f;
        int   cur = 0;
        int   t   = 1;
        while (t + 3 < Tlen) {
            CRF_STEP(1, 0, true,  h0, ROW(t + 6));   // step t   (renorm)
            CRF_STEP(0, 1, false, h1, ROW(t + 7));   // step t+1
            CRF_STEP(1, 0, false, h2, ROW(t + 8));   // step t+2
            CRF_STEP(0, 1, false, h3, ROW(t + 9));   // step t+3
            t += 4;
        }
        // remainder <= 3 steps; helpers' h0..h2 hold rows t+1..t+3
        if (t     < Tlen) CRF_STEP(1, 0, true,  h0, 0.f);
        if (t + 1 < Tlen) CRF_STEP(0, 1, false, h1, 0.f);
        if (t + 2 < Tlen) CRF_STEP(1, 0, false, h2, 0.f);
        #undef ROW

        // ---------- log_z = S + log(sum_j beta_j) (fp32 reduce) -----------
        float v = isMat ? __bfloat162float(sh_beta[cur][j]) : 0.f;
        #pragma unroll
        for (int o = 16; o; o >>= 1) v += __shfl_xor_sync(0xffffffffu, v, o);
        __syncthreads();                     // old sh_wred reads done
        if (lane == 0) sh_wred[warp] = v;
        __syncthreads();

        if (tau == 0) {
            float stot = (sh_wred[0] + sh_wred[1]) + (sh_wred[2] + sh_wred[3]);
            g_partial[b] = S + __logf(stot) - score;   // per-batch NLL
        }
        __syncthreads();                     // smem safe for next batch
    }

    // ---------- fused final reduction: last CTA sums deterministically ----
    if (tau == 0) {
        __threadfence();
        int d = atomicAdd(&g_done, 1);
        sh_last = (d == (Bn / 2 - 1));
    }
    __syncthreads();
    if (sh_last) {
        __threadfence();                 // see all CTAs' g_partial writes
        float w = g_partial[tau];        // fixed-tree: deterministic
        #pragma unroll
        for (int o = 16; o; o >>= 1) w += __shfl_xor_sync(0xffffffffu, w, o);
        if (lane == 0) sh_wred[warp] = w;
        __syncthreads();
        if (tau == 0) {
            float s = ((sh_wred[0] + sh_wred[1]) + (sh_wred[2] + sh_wred[3]))
                    + ((sh_wred[4] + sh_wred[5]) + (sh_wred[6] + sh_wred[7]));
            out[0]  = s;
            g_done  = 0;                 // reset for next graph replay
        }
    }
}

extern "C" void kernel_launch(void* const* d_in, const int* in_sizes, int n_in,
                              void* d_out, int out_size)
{
    const float* logits   = (const float*)d_in[0];
    const int*   labels   = (const int*)  d_in[1];
    const int*   seq_lens = (const int*)  d_in[2];
    const float* trans    = (const float*)d_in[3];
    float*       out      = (float*)d_out;

    crf_sched_kernel<<<32, 256>>>(seq_lens);
    crf_forward_kernel<<<Bn / 2, 256>>>(logits, labels, seq_lens, trans, out);
}

// round 14
// speedup vs baseline: 1.1888x; 1.1888x over previous
#include <cuda_runtime.h>
#include <cuda_bf16.h>

// Problem constants (fixed by the dataset): B=256, T=512, K=128
#define Bn 256
#define Tn 512
#define Kn 128
#define NSOLO 40          // solo CTAs (longest batches), 1 batch each
#define NCTA  148         // 40 solo + 108 pair CTAs = all SMs

// Device scratch (no allocs allowed).
__device__ float g_partial[Bn];
__device__ int   g_perm[Bn];   // g_perm[rank] = batch index, ascending length
__device__ int   g_done;       // zero-init; last CTA resets to 0 each run

// ---- scheduler: grid=32 x 256 threads; warp w ranks batch 8*bx+w ----------
__global__ void crf_sched_kernel(const int* __restrict__ seq_lens)
{
    const int lane = threadIdx.x & 31;
    const int i    = blockIdx.x * 8 + (threadIdx.x >> 5);
    const int Li   = seq_lens[i];
    int r = 0;
    #pragma unroll
    for (int kk = 0; kk < 8; kk++) {
        int k  = lane + 32 * kk;
        int Lk = seq_lens[k];
        r += (Lk < Li) || (Lk == Li && k < i);   // unique ranks
    }
    #pragma unroll
    for (int o = 16; o; o >>= 1) r += __shfl_xor_sync(0xffffffffu, r, o);
    if (lane == 0) g_perm[r] = i;
}

__device__ __forceinline__ float frcp(float x) {
    float q; asm("rcp.approx.f32 %0, %1;" : "=f"(q) : "f"(x));
    return q;
}

// Beta layout for PAIR mode (R11): half0 @ [0,64), half1 @ [72,136).
#define HOFF 72
#define BSLOT(j) (((j) < 64) ? (j) : ((j) + 8))

// ---- PAIR step: R11 proven half-split step (427 cyc) -----------------------
#define PAIR_STEP(LO, RENORM) do {                                           \
    const __nv_bfloat16* bp_ = sh_betaP[cur];                                \
    float cj_;                                                               \
    if (RENORM) {                                                            \
        float rr_ = __bfloat162float(bp_[0]);                                \
        float lr_ = __logf(rr_);                                             \
        S += lr_;                                                            \
        cj_ = __expf((LO) - lr_);                                            \
    } else {                                                                 \
        cj_ = __expf(LO);                                                    \
    }                                                                        \
    __nv_bfloat162 cj2_ = __float2bfloat162_rn(cj_);                         \
    const uint4* ap_ = (const uint4*)(bp_ + HOFF * h);                       \
    __nv_bfloat162 z_; z_.x = __float2bfloat16(0.f); z_.y = z_.x;            \
    __nv_bfloat162 a0_ = z_, a1_ = z_, a2_ = z_, a3_ = z_;                   \
    _Pragma("unroll")                                                        \
    for (int k_ = 0; k_ < 8; k_++) {                                         \
        uint4 v_ = ap_[k_];                                                  \
        a0_ = __hfma2(*(__nv_bfloat162*)&v_.x, eT2[4 * k_ + 0], a0_);        \
        a1_ = __hfma2(*(__nv_bfloat162*)&v_.y, eT2[4 * k_ + 1], a1_);        \
        a2_ = __hfma2(*(__nv_bfloat162*)&v_.z, eT2[4 * k_ + 2], a2_);        \
        a3_ = __hfma2(*(__nv_bfloat162*)&v_.w, eT2[4 * k_ + 3], a3_);        \
    }                                                                        \
    __nv_bfloat162 s_ = __hadd2(__hadd2(a0_, a1_), __hadd2(a2_, a3_));       \
    __nv_bfloat162 sw_ = __lowhigh2highlow(s_);                              \
    __nv_bfloat162 hs_ = __hadd2(s_, sw_);                                   \
    unsigned hu_  = __shfl_xor_sync(0xffffffffu, *(unsigned*)&hs_, 1);       \
    __nv_bfloat162 tot_ = __hadd2(hs_, *(__nv_bfloat162*)&hu_);              \
    __nv_bfloat162 nb2_ = __hmul2(tot_, cj2_);                               \
    if (!h) sh_betaP[cur ^ 1][slotj] = nb2_.x;                               \
    __syncthreads();                                                         \
    cur ^= 1;                                                                \
} while (0)

// ---- SOLO step: R13 proven full-column + helper step (~393 cyc) ------------
#define SOLO_STEP(RDBUF_, WRBUF_, REN_, HREG_, NROW_) do {                   \
    if (isMat) {                                                             \
        unsigned ceu_ = sh_ce[RDBUF_][j];                                    \
        __nv_bfloat162 cj2_ = *(__nv_bfloat162*)&ceu_;                       \
        if (REN_) {                                                          \
            float rr_ = __bfloat162float(sh_betaS[cur][0]);                  \
            S += __logf(rr_);                                                \
            cj2_ = __hmul2(cj2_, __float2bfloat162_rn(frcp(rr_)));           \
        }                                                                    \
        const uint4* ap_ = (const uint4*)sh_betaS[cur];                      \
        __nv_bfloat162 z_; z_.x = __float2bfloat16(0.f); z_.y = z_.x;        \
        __nv_bfloat162 a0_=z_,a1_=z_,a2_=z_,a3_=z_,a4_=z_,a5_=z_,a6_=z_,a7_=z_; \
        _Pragma("unroll")                                                    \
        for (int L_ = 0; L_ < 16; L_ += 2) {                                 \
            uint4 v_ = ap_[L_];                                              \
            uint4 w_ = ap_[L_ + 1];                                          \
            a0_ = __hfma2(*(__nv_bfloat162*)&v_.x, eT2[4*L_+0], a0_);        \
            a1_ = __hfma2(*(__nv_bfloat162*)&v_.y, eT2[4*L_+1], a1_);        \
            a2_ = __hfma2(*(__nv_bfloat162*)&v_.z, eT2[4*L_+2], a2_);        \
            a3_ = __hfma2(*(__nv_bfloat162*)&v_.w, eT2[4*L_+3], a3_);        \
            a4_ = __hfma2(*(__nv_bfloat162*)&w_.x, eT2[4*L_+4], a4_);        \
            a5_ = __hfma2(*(__nv_bfloat162*)&w_.y, eT2[4*L_+5], a5_);        \
            a6_ = __hfma2(*(__nv_bfloat162*)&w_.z, eT2[4*L_+6], a6_);        \
            a7_ = __hfma2(*(__nv_bfloat162*)&w_.w, eT2[4*L_+7], a7_);        \
        }                                                                    \
        __nv_bfloat162 s_ =                                                  \
            __hadd2(__hadd2(__hadd2(a0_, a1_), __hadd2(a2_, a3_)),           \
                    __hadd2(__hadd2(a4_, a5_), __hadd2(a6_, a7_)));          \
        s_ = __hmul2(s_, cj2_);                                              \
        __nv_bfloat162 sw_ = __lowhigh2highlow(s_);                          \
        __nv_bfloat162 tot_ = __hadd2(s_, sw_);                              \
        sh_betaS[cur ^ 1][j] = tot_.x;                                       \
    } else {                                                                 \
        __nv_bfloat162 ce_ = __float2bfloat162_rn(__expf(HREG_));            \
        sh_ce[WRBUF_][j] = *(unsigned*)&ce_;                                 \
        HREG_ = NROW_;                                                       \
    }                                                                        \
    __syncthreads();                                                         \
    cur ^= 1;                                                                \
} while (0)

// Hybrid schedule over 148 SMs:
//   CTAs 0..39   : SOLO, batch perm[255-c] (the 40 longest), full-column
//                  engine at ~393 cyc/step.
//   CTAs 40..147 : PAIR, batches perm[k] + perm[215-k] (k=c-40), sums ~430,
//                  half-split engine at ~427 cyc/step.
// Makespan: max(512*393, 430*427) ~ 201K cyc vs R11's 513*427 ~ 219K.
__global__ __launch_bounds__(256, 1) void crf_forward_kernel(
    const float* __restrict__ logits,   // [B, T, K]
    const int*   __restrict__ labels,   // [B, T]
    const int*   __restrict__ seq_lens, // [B]
    const float* __restrict__ trans,    // [K, K] trans[i*K + j]
    float* __restrict__ out)
{
    __shared__ __align__(16) __nv_bfloat16 sh_betaP[2][144];   // pair mode
    __shared__ __align__(16) __nv_bfloat16 sh_betaS[2][Kn];    // solo mode
    __shared__ unsigned sh_ce[2][Kn];                          // solo cj
    __shared__ float sh_wred[8];
    __shared__ int   sh_last;

    const int c    = blockIdx.x;          // 0..147
    const int tau  = threadIdx.x;         // 0..255
    const int lane = tau & 31;
    const int warp = tau >> 5;

    __nv_bfloat162 eT2[64];

    if (c < NSOLO) {
        // =========================== SOLO MODE ===========================
        const bool isMat = (tau < Kn);
        const int  j     = isMat ? tau : (tau - Kn);
        const int  b     = g_perm[(Bn - 1) - c];

        if (isMat) {
            #pragma unroll
            for (int k = 0; k < 64; k++) {
                float e0 = __expf(trans[(2 * k)     * Kn + j]);
                float e1 = __expf(trans[(2 * k + 1) * Kn + j]);
                eT2[k] = __floats2bfloat162_rn(e0, e1);
            }
        }

        const int    Tlen = seq_lens[b];
        const float* lg   = logits + (size_t)b * Tn * Kn;
        const int*   lb   = labels + b * Tn;

        float sc = 0.f;
        for (int t = tau; t < Tlen; t += 256) {
            int y = lb[t];
            sc += lg[t * Kn + y];
            if (t >= 1) sc += trans[lb[t - 1] * Kn + y];
        }
        #pragma unroll
        for (int o = 16; o; o >>= 1) sc += __shfl_xor_sync(0xffffffffu, sc, o);
        if (lane == 0) sh_wred[warp] = sc;

        #define ROWS(tt) lg[(((tt) < Tn) ? (tt) : (Tn - 1)) * Kn + j]
        float h0 = 0.f, h1 = 0.f, h2 = 0.f, h3 = 0.f;
        if (isMat) {
            sh_betaS[0][j] = __float2bfloat16(__expf(lg[j]));
        } else {
            __nv_bfloat162 ce0 = __float2bfloat162_rn(__expf(ROWS(1)));
            sh_ce[1][j] = *(unsigned*)&ce0;
            h0 = ROWS(2); h1 = ROWS(3); h2 = ROWS(4); h3 = ROWS(5);
        }
        __syncthreads();
        float score = 0.f;
        #pragma unroll
        for (int w = 0; w < 8; w++) score += sh_wred[w];

        float S = 0.f;
        int cur = 0, t = 1;
        while (t + 3 < Tlen) {
            SOLO_STEP(1, 0, true,  h0, ROWS(t + 6));
            SOLO_STEP(0, 1, false, h1, ROWS(t + 7));
            SOLO_STEP(1, 0, false, h2, ROWS(t + 8));
            SOLO_STEP(0, 1, false, h3, ROWS(t + 9));
            t += 4;
        }
        if (t     < Tlen) SOLO_STEP(1, 0, true,  h0, 0.f);
        if (t + 1 < Tlen) SOLO_STEP(0, 1, false, h1, 0.f);
        if (t + 2 < Tlen) SOLO_STEP(1, 0, false, h2, 0.f);
        #undef ROWS

        float v = isMat ? __bfloat162float(sh_betaS[cur][j]) : 0.f;
        #pragma unroll
        for (int o = 16; o; o >>= 1) v += __shfl_xor_sync(0xffffffffu, v, o);
        __syncthreads();
        if (lane == 0) sh_wred[warp] = v;
        __syncthreads();
        if (tau == 0) {
            float stot = (sh_wred[0] + sh_wred[1]) + (sh_wred[2] + sh_wred[3]);
            g_partial[b] = S + __logf(stot) - score;
        }
        __syncthreads();
    } else {
        // =========================== PAIR MODE ===========================
        const int j     = tau >> 1;       // column 0..127
        const int h     = tau & 1;        // half
        const int slotj = BSLOT(j);
        const int k     = c - NSOLO;      // 0..107
        const int bA    = g_perm[k];
        const int bB    = g_perm[215 - k];

        #pragma unroll
        for (int kk = 0; kk < 32; kk++) {
            float e0 = __expf(trans[(64 * h + 2 * kk)     * Kn + j]);
            float e1 = __expf(trans[(64 * h + 2 * kk + 1) * Kn + j]);
            eT2[kk] = __floats2bfloat162_rn(e0, e1);
        }

        for (int p = 0; p < 2; p++) {
            const int b = p ? bB : bA;
            const int    Tlen = seq_lens[b];
            const float* lg   = logits + (size_t)b * Tn * Kn;
            const int*   lb   = labels + b * Tn;

            float sc = 0.f;
            for (int t = tau; t < Tlen; t += 256) {
                int y = lb[t];
                sc += lg[t * Kn + y];
                if (t >= 1) sc += trans[lb[t - 1] * Kn + y];
            }
            #pragma unroll
            for (int o = 16; o; o >>= 1)
                sc += __shfl_xor_sync(0xffffffffu, sc, o);
            if (lane == 0) sh_wred[warp] = sc;

            if (!h) sh_betaP[0][slotj] = __float2bfloat16(__expf(lg[j]));

            #define ROWP(tt) lg[(((tt) < Tn) ? (tt) : (Tn - 1)) * Kn + j]
            float la0 = ROWP(1), la1 = ROWP(2), la2 = ROWP(3), la3 = ROWP(4);

            __syncthreads();
            float score = 0.f;
            #pragma unroll
            for (int w = 0; w < 8; w++) score += sh_wred[w];

            float S = 0.f;
            int cur = 0, t = 1;
            while (t + 3 < Tlen) {
                PAIR_STEP(la0, true);  la0 = ROWP(t + 4);
                PAIR_STEP(la1, false); la1 = ROWP(t + 5);
                PAIR_STEP(la2, false); la2 = ROWP(t + 6);
                PAIR_STEP(la3, false); la3 = ROWP(t + 7);
                t += 4;
            }
            if (t     < Tlen) PAIR_STEP(la0, true);
            if (t + 1 < Tlen) PAIR_STEP(la1, false);
            if (t + 2 < Tlen) PAIR_STEP(la2, false);
            #undef ROWP

            __syncthreads();
            float v = (tau < Kn) ? __bfloat162float(sh_betaP[cur][BSLOT(tau)])
                                 : 0.f;
            #pragma unroll
            for (int o = 16; o; o >>= 1)
                v += __shfl_xor_sync(0xffffffffu, v, o);
            if (lane == 0) sh_wred[warp] = v;
            __syncthreads();

            if (tau == 0) {
                float stot = ((sh_wred[0] + sh_wred[1]) + (sh_wred[2] + sh_wred[3]))
                           + ((sh_wred[4] + sh_wred[5]) + (sh_wred[6] + sh_wred[7]));
                g_partial[b] = S + __logf(stot) - score;
            }
            __syncthreads();
        }
    }

    // ---------- fused final reduction: last CTA sums deterministically ----
    if (tau == 0) {
        __threadfence();
        int d = atomicAdd(&g_done, 1);
        sh_last = (d == (NCTA - 1));
    }
    __syncthreads();
    if (sh_last) {
        __threadfence();                 // see all CTAs' g_partial writes
        float w = g_partial[tau];        // fixed-tree: deterministic
        #pragma unroll
        for (int o = 16; o; o >>= 1) w += __shfl_xor_sync(0xffffffffu, w, o);
        if (lane == 0) sh_wred[warp] = w;
        __syncthreads();
        if (tau == 0) {
            float s = ((sh_wred[0] + sh_wred[1]) + (sh_wred[2] + sh_wred[3]))
                    + ((sh_wred[4] + sh_wred[5]) + (sh_wred[6] + sh_wred[7]));
            out[0]  = s;
            g_done  = 0;                 // reset for next graph replay
        }
    }
}

extern "C" void kernel_launch(void* const* d_in, const int* in_sizes, int n_in,
                              void* d_out, int out_size)
{
    const float* logits   = (const float*)d_in[0];
    const int*   labels   = (const int*)  d_in[1];
    const int*   seq_lens = (const int*)  d_in[2];
    const float* trans    = (const float*)d_in[3];
    float*       out      = (float*)d_out;

    crf_sched_kernel<<<32, 256>>>(seq_lens);
    crf_forward_kernel<<<NCTA, 256>>>(logits, labels, seq_lens, trans, out);
}